// round 1
// baseline (speedup 1.0000x reference)
#include <cuda_runtime.h>
#include <cuda_bf16.h>
#include <math.h>

// ---------------------------------------------------------------------------
// AsymmetricLossCustomPriorityRankNewNegOne
// B=4096, C=9605, L=20. Only union-of-whitelist columns matter (~1000/9605).
// ---------------------------------------------------------------------------

#define MAXC 16384

__device__ unsigned            g_bits[MAXC];     // per-class group bitmask (L<=32)
__device__ unsigned long long  g_pack[MAXC];     // compacted (bits<<32 | c), sorted by c
__device__ int                 g_ucount;
__device__ int                 g_is_u8;          // wl_masks element width detector

// monotone float <-> unsigned encoding for atomicMax on signed floats
__device__ __forceinline__ unsigned enc_f(float f) {
    unsigned u = __float_as_uint(f);
    return (u & 0x80000000u) ? ~u : (u | 0x80000000u);
}
__device__ __forceinline__ float dec_f(unsigned u) {
    return __uint_as_float((u & 0x80000000u) ? (u & 0x7fffffffu) : ~u);
}

__device__ __forceinline__ float sigmoidf_(float x) {
    return 1.0f / (1.0f + expf(-x));
}

// rank loss: d = x2 - x1 + margin; s = sigmoid(10 d); d>0 -> 2s else s
__device__ __forceinline__ float rank_loss_(float x1, float x2) {
    float d = x2 - x1 + 0.05f;
    float s = sigmoidf_(10.0f * d);
    return (d > 0.0f) ? 2.0f * s : s;
}

// --- kernel 0: zero output -------------------------------------------------
__global__ void zero_out_kernel(float* out, int n) {
    int i = blockIdx.x * blockDim.x + threadIdx.x;
    if (i < n) out[i] = 0.0f;
}

// --- kernel 1: detect wl_masks storage width --------------------------------
// If the harness passes bool as uint8, reading the buffer as int32 yields
// packed-byte values like 0x01010101 (>1). If it passes int32 0/1, all probed
// values are <= 1.
__global__ void detect_kernel(const unsigned int* wl_as_u32, int n_probe) {
    if (threadIdx.x == 0 && blockIdx.x == 0) {
        int u8 = 0;
        for (int i = 0; i < n_probe; i++) {
            if (wl_as_u32[i] > 1u) { u8 = 1; break; }
        }
        g_is_u8 = u8;
    }
}

// --- kernel 2: per-class group bitmask --------------------------------------
__global__ void build_bits_kernel(const void* wl, int C, int L) {
    int c = blockIdx.x * blockDim.x + threadIdx.x;
    if (c >= C) return;
    unsigned b = 0;
    if (g_is_u8) {
        const unsigned char* m = (const unsigned char*)wl;
        for (int l = 0; l < L; l++)
            if (m[(size_t)l * C + c]) b |= (1u << l);
    } else {
        const int* m = (const int*)wl;
        for (int l = 0; l < L; l++)
            if (m[(size_t)l * C + c]) b |= (1u << l);
    }
    g_bits[c] = b;
}

// --- kernel 3: ordered compaction (single block) -----------------------------
__global__ void compact_kernel(int C) {
    __shared__ int warpCnt[32];
    __shared__ int warpOff[32];
    __shared__ int sbase;
    int lane = threadIdx.x & 31;
    int wid  = threadIdx.x >> 5;
    int nw   = blockDim.x >> 5;
    if (threadIdx.x == 0) sbase = 0;
    __syncthreads();
    for (int start = 0; start < C; start += blockDim.x) {
        int c = start + threadIdx.x;
        unsigned b = (c < C) ? g_bits[c] : 0u;
        unsigned ballot = __ballot_sync(0xffffffffu, b != 0u);
        if (lane == 0) warpCnt[wid] = __popc(ballot);
        __syncthreads();
        if (threadIdx.x == 0) {
            int acc = sbase;
            for (int w = 0; w < nw; w++) { warpOff[w] = acc; acc += warpCnt[w]; }
            sbase = acc;
        }
        __syncthreads();
        if (b) {
            int pos = warpOff[wid] + __popc(ballot & ((1u << lane) - 1u));
            g_pack[pos] = ((unsigned long long)b << 32) | (unsigned)c;
        }
        __syncthreads();
    }
    if (threadIdx.x == 0) g_ucount = sbase;
}

// --- kernel 4: per-row loss (one block per row) ------------------------------
__global__ __launch_bounds__(256)
void row_loss_kernel(const float* __restrict__ x,
                     const int*   __restrict__ y,
                     const int*   __restrict__ yneg,
                     int C, float* __restrict__ out) {
    __shared__ unsigned sG[32];      // per-group max key
    __shared__ unsigned sPres;       // present group bitmask
    __shared__ unsigned sNon;        // union max key
    __shared__ unsigned sWrong;      // y_neg-masked max key

    if (threadIdx.x < 32) sG[threadIdx.x] = 0u;
    if (threadIdx.x == 0) { sPres = 0u; sNon = 0u; sWrong = 0u; }
    __syncthreads();

    const int row = blockIdx.x;
    const size_t base = (size_t)row * C;
    const float* xr  = x    + base;
    const int*   yr  = y    + base;
    const int*   ynr = yneg + base;

    const int n = g_ucount;
    unsigned locNon = 0u, locWrong = 0u, locPres = 0u;

    for (int i = threadIdx.x; i < n; i += blockDim.x) {
        unsigned long long p = g_pack[i];
        int c        = (int)(p & 0xffffffffull);
        unsigned bits = (unsigned)(p >> 32);
        float xv = __ldg(xr + c);
        unsigned key = enc_f(xv);
        locNon = max(locNon, key);
        if (__ldg(ynr + c) != 0) locWrong = max(locWrong, key);
        if (__ldg(yr  + c) != 0) locPres |= bits;
        unsigned bb = bits;
        while (bb) {
            int l = __ffs(bb) - 1;
            bb &= bb - 1u;
            atomicMax(&sG[l], key);
        }
    }

    // warp-reduce locals, then shared atomics once per warp
    for (int off = 16; off > 0; off >>= 1) {
        locNon   = max(locNon,   __shfl_down_sync(0xffffffffu, locNon,   off));
        locWrong = max(locWrong, __shfl_down_sync(0xffffffffu, locWrong, off));
        locPres |= __shfl_down_sync(0xffffffffu, locPres, off);
    }
    if ((threadIdx.x & 31) == 0) {
        atomicMax(&sNon, locNon);
        atomicMax(&sWrong, locWrong);
        atomicOr(&sPres, locPres);
    }
    __syncthreads();

    if (threadIdx.x == 0) {
        unsigned pres = sPres;
        float loss;
        if (pres) {
            int fl = __ffs(pres) - 1;                  // first (lowest) group with a positive
            float x1 = sigmoidf_(dec_f(sG[fl]));       // group max of sigmoid
            loss = rank_loss_(x1, 0.5f);               // _rank_loss(x1_wl, 0.5, 0.05)
        } else {
            float mNon   = sigmoidf_(dec_f(sNon));
            float mWrong = sigmoidf_(dec_f(sWrong));
            loss = 0.5f * rank_loss_(0.5f, mNon)       // (1-ALPHA) * rank(0.5, max_non_other)
                 + 0.5f * rank_loss_(0.5f, mWrong);    //  ALPHA    * rank(0.5, max_wrong)
        }
        atomicAdd(out, loss);
    }
}

// ---------------------------------------------------------------------------
extern "C" void kernel_launch(void* const* d_in, const int* in_sizes, int n_in,
                              void* d_out, int out_size) {
    const float* x    = (const float*)d_in[0];
    const int*   y    = (const int*)d_in[1];
    const int*   yneg = (const int*)d_in[2];
    const void*  wl   = d_in[3];

    const int C = 9605;                       // fixed problem shape
    const int L = in_sizes[3] / C;            // 20
    const int B = in_sizes[0] / C;            // 4096

    float* out = (float*)d_out;

    zero_out_kernel<<<(out_size + 255) / 256, 256>>>(out, out_size);

    int n_probe = in_sizes[3] < 256 ? in_sizes[3] : 256;
    detect_kernel<<<1, 32>>>((const unsigned int*)wl, n_probe);

    build_bits_kernel<<<(C + 255) / 256, 256>>>(wl, C, L);

    compact_kernel<<<1, 1024>>>(C);

    row_loss_kernel<<<B, 256>>>(x, y, yneg, C, out);
}

// round 2
// speedup vs baseline: 1.0524x; 1.0524x over previous
#include <cuda_runtime.h>
#include <cuda_bf16.h>
#include <math.h>

// ---------------------------------------------------------------------------
// AsymmetricLossCustomPriorityRankNewNegOne  (B=4096, C=9605, L=20)
// Only union-of-whitelist columns matter (~1000/9605). Fast path assumes the
// union is a contiguous column range with one group per class (verified on
// device each launch); generic slow path otherwise.
// ---------------------------------------------------------------------------

#define MAXC 16384

__device__ unsigned            g_bits[MAXC];   // per-class group bitmask (L<=32)
__device__ unsigned char       g_gid[MAXC];    // first group id per class (255 = none)
__device__ unsigned long long  g_pack[MAXC];   // compacted (bits<<32 | c)
__device__ int                 g_ucount;
__device__ int                 g_cmin;
__device__ int                 g_cmax;
__device__ int                 g_multi;        // any class in >1 group?
__device__ int                 g_is_u8;        // wl_masks stored as bytes?

// monotone float <-> unsigned encoding for atomicMax
__device__ __forceinline__ unsigned enc_f(float f) {
    unsigned u = __float_as_uint(f);
    return (u & 0x80000000u) ? ~u : (u | 0x80000000u);
}
__device__ __forceinline__ float dec_f(unsigned u) {
    return __uint_as_float((u & 0x80000000u) ? (u & 0x7fffffffu) : ~u);
}

__device__ __forceinline__ float sigmoidf_(float x) {
    return 1.0f / (1.0f + expf(-x));
}

// rank loss: d = x2 - x1 + 0.05; s = sigmoid(10 d); d>0 -> 2s else s
__device__ __forceinline__ float rank_loss_(float x1, float x2) {
    float d = x2 - x1 + 0.05f;
    float s = sigmoidf_(10.0f * d);
    return (d > 0.0f) ? 2.0f * s : s;
}

// --- kernel 1: init + detect (single tiny block) -----------------------------
__global__ void init_kernel(float* out, int out_size,
                            const unsigned int* wl_as_u32, int n_probe) {
    int t = threadIdx.x;
    for (int i = t; i < out_size; i += blockDim.x) out[i] = 0.0f;
    if (t == 0) {
        g_ucount = 0;
        g_cmin   = 0x7fffffff;
        g_cmax   = -1;
        g_multi  = 0;
        int u8 = 0;
        for (int i = 0; i < n_probe; i++)
            if (wl_as_u32[i] > 1u) { u8 = 1; break; }
        g_is_u8 = u8;
    }
}

// --- kernel 2: per-class group bitmask + union range stats -------------------
__global__ void build_bits_kernel(const void* wl, int C, int L) {
    __shared__ int bmin, bmax, bmulti;
    if (threadIdx.x == 0) { bmin = 0x7fffffff; bmax = -1; bmulti = 0; }
    __syncthreads();

    int c = blockIdx.x * blockDim.x + threadIdx.x;
    unsigned b = 0;
    if (c < C) {
        if (g_is_u8) {
            const unsigned char* m = (const unsigned char*)wl;
            #pragma unroll 4
            for (int l = 0; l < L; l++)
                if (m[(size_t)l * C + c]) b |= (1u << l);
        } else {
            const int* m = (const int*)wl;
            #pragma unroll 4
            for (int l = 0; l < L; l++)
                if (m[(size_t)l * C + c]) b |= (1u << l);
        }
        g_bits[c] = b;
        g_gid[c]  = b ? (unsigned char)(__ffs(b) - 1) : (unsigned char)255;
        if (b) {
            atomicMin(&bmin, c);
            atomicMax(&bmax, c);
            if (__popc(b) > 1) bmulti = 1;
        }
    }
    __syncthreads();
    if (threadIdx.x == 0 && bmax >= 0) {
        atomicMin(&g_cmin, bmin);
        atomicMax(&g_cmax, bmax);
        if (bmulti) g_multi = 1;
    }
}

// --- kernel 3: parallel compaction (unordered across blocks) -----------------
__global__ void compact_kernel(int C) {
    __shared__ int woff[8];
    __shared__ int sbase;
    int c    = blockIdx.x * 256 + threadIdx.x;
    int lane = threadIdx.x & 31;
    int wid  = threadIdx.x >> 5;

    unsigned b = (c < C) ? g_bits[c] : 0u;
    unsigned ballot = __ballot_sync(0xffffffffu, b != 0u);
    if (lane == 0) woff[wid] = __popc(ballot);
    __syncthreads();
    if (threadIdx.x == 0) {
        int acc = 0;
        #pragma unroll
        for (int w = 0; w < 8; w++) { int t = woff[w]; woff[w] = acc; acc += t; }
        sbase = atomicAdd(&g_ucount, acc);
    }
    __syncthreads();
    if (b) {
        int pos = sbase + woff[wid] + __popc(ballot & ((1u << lane) - 1u));
        g_pack[pos] = ((unsigned long long)b << 32) | (unsigned)c;
    }
}

// --- kernel 4: per-row loss (one block per row) -------------------------------
__global__ __launch_bounds__(256)
void row_loss_kernel(const float* __restrict__ x,
                     const int*   __restrict__ y,
                     const int*   __restrict__ yneg,
                     int C, float* __restrict__ out) {
    const unsigned KNEG = enc_f(-1e30f);

    __shared__ unsigned sG[32];
    __shared__ unsigned sPres, sNon, sWrong;

    if (threadIdx.x < 32) sG[threadIdx.x] = KNEG;
    if (threadIdx.x == 0) { sPres = 0u; sNon = KNEG; sWrong = KNEG; }
    __syncthreads();

    const int row  = blockIdx.x;
    const size_t base = (size_t)row * C;
    const int n    = g_ucount;
    const int cmin = g_cmin;
    const bool fast = (!g_multi) && (g_cmax - cmin + 1 == n);

    unsigned locNon = KNEG, locWrong = KNEG, locPres = 0u;

    if (fast) {
        const float* __restrict__ xr  = x    + base + cmin;
        const int*   __restrict__ yr  = y    + base + cmin;
        const int*   __restrict__ ynr = yneg + base + cmin;
        const unsigned char* __restrict__ gr = g_gid + cmin;

        int i = threadIdx.x;
        for (; i + 768 < n; i += 1024) {
            float xv[4]; int yv[4], ynv[4]; unsigned char gv[4];
            #pragma unroll
            for (int j = 0; j < 4; j++) {
                int k = i + j * 256;
                xv[j]  = __ldg(xr + k);
                yv[j]  = __ldg(yr + k);
                ynv[j] = __ldg(ynr + k);
                gv[j]  = __ldg(gr + k);
            }
            #pragma unroll
            for (int j = 0; j < 4; j++) {
                unsigned key = enc_f(xv[j]);
                locNon = max(locNon, key);
                if (ynv[j]) locWrong = max(locWrong, key);
                if (yv[j])  locPres |= (1u << gv[j]);
                atomicMax(&sG[gv[j]], key);
            }
        }
        for (; i < n; i += 256) {
            float xv = __ldg(xr + i);
            unsigned key = enc_f(xv);
            unsigned char g = __ldg(gr + i);
            locNon = max(locNon, key);
            if (__ldg(ynr + i)) locWrong = max(locWrong, key);
            if (__ldg(yr + i))  locPres |= (1u << g);
            atomicMax(&sG[g], key);
        }
    } else {
        for (int i = threadIdx.x; i < n; i += 256) {
            unsigned long long p = g_pack[i];
            int c         = (int)(p & 0xffffffffull);
            unsigned bits = (unsigned)(p >> 32);
            float xv = __ldg(x + base + c);
            unsigned key = enc_f(xv);
            locNon = max(locNon, key);
            if (__ldg(yneg + base + c) != 0) locWrong = max(locWrong, key);
            if (__ldg(y    + base + c) != 0) locPres |= bits;
            unsigned bb = bits;
            while (bb) {
                int l = __ffs(bb) - 1;
                bb &= bb - 1u;
                atomicMax(&sG[l], key);
            }
        }
    }

    // warp-reduce locals, then one shared atomic per warp
    #pragma unroll
    for (int off = 16; off > 0; off >>= 1) {
        locNon   = max(locNon,   __shfl_down_sync(0xffffffffu, locNon,   off));
        locWrong = max(locWrong, __shfl_down_sync(0xffffffffu, locWrong, off));
        locPres |= __shfl_down_sync(0xffffffffu, locPres, off);
    }
    if ((threadIdx.x & 31) == 0) {
        atomicMax(&sNon, locNon);
        atomicMax(&sWrong, locWrong);
        atomicOr(&sPres, locPres);
    }
    __syncthreads();

    if (threadIdx.x == 0) {
        unsigned pres = sPres;
        float loss;
        if (pres) {
            int fl = __ffs(pres) - 1;
            float x1 = sigmoidf_(dec_f(sG[fl]));
            loss = rank_loss_(x1, 0.5f);
        } else {
            float mNon   = sigmoidf_(dec_f(sNon));
            float mWrong = sigmoidf_(dec_f(sWrong));
            loss = 0.5f * rank_loss_(0.5f, mNon)
                 + 0.5f * rank_loss_(0.5f, mWrong);
        }
        atomicAdd(out, loss);
    }
}

// ---------------------------------------------------------------------------
extern "C" void kernel_launch(void* const* d_in, const int* in_sizes, int n_in,
                              void* d_out, int out_size) {
    const float* x    = (const float*)d_in[0];
    const int*   y    = (const int*)d_in[1];
    const int*   yneg = (const int*)d_in[2];
    const void*  wl   = d_in[3];

    const int C = 9605;
    const int L = in_sizes[3] / C;            // 20
    const int B = in_sizes[0] / C;            // 4096

    float* out = (float*)d_out;

    int n_probe = 256;
    init_kernel<<<1, 256>>>(out, out_size, (const unsigned int*)wl, n_probe);

    build_bits_kernel<<<(C + 255) / 256, 256>>>(wl, C, L);

    compact_kernel<<<(C + 255) / 256, 256>>>(C);

    row_loss_kernel<<<B, 256>>>(x, y, yneg, C, out);
}

// round 3
// speedup vs baseline: 2.4499x; 2.3280x over previous
#include <cuda_runtime.h>
#include <cuda_bf16.h>
#include <math.h>

// ---------------------------------------------------------------------------
// AsymmetricLossCustomPriorityRankNewNegOne  (B=4096, C=9605, L=20)
// Fast path (device-verified): union of whitelist classes is a contiguous
// range [cmin, cmin+n), each class in exactly one group, group id computable
// as (j*M)>>22 (uniform group size). Vectorized 128-bit loads.
// ---------------------------------------------------------------------------

#define MAXC 16384

__device__ unsigned            g_bits[MAXC];   // per-class group bitmask (L<=32)
__device__ unsigned long long  g_pack[MAXC];   // compacted (bits<<32 | c)  [slow path]
__device__ int                 g_ucount;
__device__ int                 g_cmin;
__device__ int                 g_cmax;
__device__ int                 g_notfast;      // disable fast path
__device__ int                 g_gs;           // size of group 0 (candidate uniform size)
__device__ int                 g_is_u8;        // wl_masks stored as bytes?

__device__ __forceinline__ unsigned enc_f(float f) {
    unsigned u = __float_as_uint(f);
    return (u & 0x80000000u) ? ~u : (u | 0x80000000u);
}
__device__ __forceinline__ float dec_f(unsigned u) {
    return __uint_as_float((u & 0x80000000u) ? (u & 0x7fffffffu) : ~u);
}
__device__ __forceinline__ float sigmoidf_(float x) {
    return 1.0f / (1.0f + expf(-x));
}
// rank loss: d = x2 - x1 + 0.05; s = sigmoid(10 d); d>0 -> 2s else s
__device__ __forceinline__ float rank_loss_(float x1, float x2) {
    float d = x2 - x1 + 0.05f;
    float s = sigmoidf_(10.0f * d);
    return (d > 0.0f) ? 2.0f * s : s;
}

// --- kernel 1: init + parallel width detect ----------------------------------
__global__ void init_kernel(float* out, int out_size,
                            const unsigned int* wl_as_u32, int n_probe) {
    __shared__ int flag;
    int t = threadIdx.x;
    if (t == 0) flag = 0;
    __syncthreads();
    for (int i = t; i < out_size; i += blockDim.x) out[i] = 0.0f;
    if (t < n_probe && wl_as_u32[t] > 1u) flag = 1;
    __syncthreads();
    if (t == 0) {
        g_is_u8   = flag;
        g_ucount  = 0;
        g_cmin    = 0x7fffffff;
        g_cmax    = -1;
        g_notfast = 0;
        g_gs      = 0;
    }
}

// --- kernel 2: per-class group bitmask + stats --------------------------------
__global__ void build_bits_kernel(const void* wl, int C, int L) {
    __shared__ int bmin, bmax, bbad, bgs;
    if (threadIdx.x == 0) { bmin = 0x7fffffff; bmax = -1; bbad = 0; bgs = 0; }
    __syncthreads();

    int c = blockIdx.x * blockDim.x + threadIdx.x;
    unsigned b = 0;
    if (c < C) {
        if (g_is_u8) {
            const unsigned char* m = (const unsigned char*)wl;
            #pragma unroll 4
            for (int l = 0; l < L; l++)
                if (m[(size_t)l * C + c]) b |= (1u << l);
        } else {
            const int* m = (const int*)wl;
            #pragma unroll 4
            for (int l = 0; l < L; l++)
                if (m[(size_t)l * C + c]) b |= (1u << l);
        }
        g_bits[c] = b;
        if (b) {
            atomicMin(&bmin, c);
            atomicMax(&bmax, c);
            if (__popc(b) > 1) bbad = 1;
            if (b == 1u) atomicAdd(&bgs, 1);   // class belongs to group 0 only
        }
    }
    __syncthreads();
    if (threadIdx.x == 0) {
        if (bmax >= 0) { atomicMin(&g_cmin, bmin); atomicMax(&g_cmax, bmax); }
        if (bbad) g_notfast = 1;
        if (bgs)  atomicAdd(&g_gs, bgs);
    }
}

// --- kernel 3: compaction + fast-path verification ----------------------------
__global__ void compact_kernel(int C) {
    __shared__ int woff[8];
    __shared__ int sbase;
    int c    = blockIdx.x * 256 + threadIdx.x;
    int lane = threadIdx.x & 31;
    int wid  = threadIdx.x >> 5;

    unsigned b = (c < C) ? g_bits[c] : 0u;
    unsigned ballot = __ballot_sync(0xffffffffu, b != 0u);
    if (lane == 0) woff[wid] = __popc(ballot);
    __syncthreads();
    if (threadIdx.x == 0) {
        int acc = 0;
        #pragma unroll
        for (int w = 0; w < 8; w++) { int t = woff[w]; woff[w] = acc; acc += t; }
        sbase = atomicAdd(&g_ucount, acc);
    }
    __syncthreads();
    if (b) {
        int pos = sbase + woff[wid] + __popc(ballot & ((1u << lane) - 1u));
        g_pack[pos] = ((unsigned long long)b << 32) | (unsigned)c;

        // verify the magic-division gid formula exactly for this class
        int gs = g_gs;
        if (gs > 0) {
            unsigned M = (4194304u + (unsigned)gs - 1u) / (unsigned)gs;
            unsigned j = (unsigned)(c - g_cmin);
            unsigned gmagic = (j * M) >> 22;
            if ((int)gmagic != (__ffs(b) - 1) || gmagic >= 32u) g_notfast = 1;
        } else {
            g_notfast = 1;
        }
    }
}

// --- kernel 4: per-row loss (one block per row) --------------------------------
__global__ __launch_bounds__(256)
void row_loss_kernel(const float* __restrict__ x,
                     const int*   __restrict__ y,
                     const int*   __restrict__ yneg,
                     int C, float* __restrict__ out) {
    const unsigned KNEG = enc_f(-1e30f);

    __shared__ unsigned sG[32];
    __shared__ unsigned sPres, sNon, sWrong;

    if (threadIdx.x < 32) sG[threadIdx.x] = KNEG;
    if (threadIdx.x == 0) { sPres = 0u; sNon = KNEG; sWrong = KNEG; }
    __syncthreads();

    const int row  = blockIdx.x;
    const int n    = g_ucount;
    const int cmin = g_cmin;
    const bool fast = (!g_notfast) && (g_cmax - cmin + 1 == n);
    const long long base = (long long)row * C + cmin;

    unsigned locNon = KNEG, locWrong = KNEG, locPres = 0u;

    if (fast) {
        const int gs = g_gs;
        const unsigned M = (4194304u + (unsigned)gs - 1u) / (unsigned)gs;
        const float* __restrict__ xr  = x    + base;
        const int*   __restrict__ yr  = y    + base;
        const int*   __restrict__ ynr = yneg + base;

        int p = (int)((4 - (base & 3)) & 3);          // front peel to 16B alignment
        if (p > n) p = n;
        const int nv = (n - p) >> 2;                   // number of vec4 chunks
        const int tail_start = p + 4 * nv;
        const int ntail = n - tail_start;

        for (int i = threadIdx.x; i < nv; i += 256) {
            const int j0 = p + 4 * i;
            const float4 xv  = *(const float4*)(xr  + j0);
            const int4   yv  = *(const int4*)  (yr  + j0);
            const int4   ynv = *(const int4*)  (ynr + j0);

            unsigned k0 = enc_f(xv.x), k1 = enc_f(xv.y),
                     k2 = enc_f(xv.z), k3 = enc_f(xv.w);
            unsigned kmax = max(max(k0, k1), max(k2, k3));
            locNon = max(locNon, kmax);

            if (ynv.x) locWrong = max(locWrong, k0);
            if (ynv.y) locWrong = max(locWrong, k1);
            if (ynv.z) locWrong = max(locWrong, k2);
            if (ynv.w) locWrong = max(locWrong, k3);

            const unsigned g0 = ((unsigned)j0 * M) >> 22;
            const unsigned g3 = ((unsigned)(j0 + 3) * M) >> 22;
            if (g0 == g3) {
                if (yv.x | yv.y | yv.z | yv.w) locPres |= (1u << g0);
                atomicMax(&sG[g0], kmax);
            } else {
                const unsigned g1 = ((unsigned)(j0 + 1) * M) >> 22;
                const unsigned g2 = ((unsigned)(j0 + 2) * M) >> 22;
                if (yv.x) locPres |= (1u << g0);
                if (yv.y) locPres |= (1u << g1);
                if (yv.z) locPres |= (1u << g2);
                if (yv.w) locPres |= (1u << g3);
                atomicMax(&sG[g0], k0);
                atomicMax(&sG[g1], k1);
                atomicMax(&sG[g2], k2);
                atomicMax(&sG[g3], k3);
            }
        }

        // peel [0,p) and tail [tail_start,n), scalar
        for (int t = threadIdx.x; t < p + ntail; t += 256) {
            const int j = (t < p) ? t : (tail_start + (t - p));
            const float xvv = __ldg(xr + j);
            const unsigned key = enc_f(xvv);
            const unsigned g = ((unsigned)j * M) >> 22;
            locNon = max(locNon, key);
            if (__ldg(ynr + j)) locWrong = max(locWrong, key);
            if (__ldg(yr + j))  locPres |= (1u << g);
            atomicMax(&sG[g], key);
        }
    } else {
        // generic slow path over compacted (bits, class) pairs
        for (int i = threadIdx.x; i < n; i += 256) {
            unsigned long long pk = g_pack[i];
            int c         = (int)(pk & 0xffffffffull);
            unsigned bits = (unsigned)(pk >> 32);
            const long long o = (long long)row * C + c;
            float xv = __ldg(x + o);
            unsigned key = enc_f(xv);
            locNon = max(locNon, key);
            if (__ldg(yneg + o) != 0) locWrong = max(locWrong, key);
            if (__ldg(y    + o) != 0) locPres |= bits;
            unsigned bb = bits;
            while (bb) {
                int l = __ffs(bb) - 1;
                bb &= bb - 1u;
                atomicMax(&sG[l], key);
            }
        }
    }

    #pragma unroll
    for (int off = 16; off > 0; off >>= 1) {
        locNon   = max(locNon,   __shfl_down_sync(0xffffffffu, locNon,   off));
        locWrong = max(locWrong, __shfl_down_sync(0xffffffffu, locWrong, off));
        locPres |= __shfl_down_sync(0xffffffffu, locPres, off);
    }
    if ((threadIdx.x & 31) == 0) {
        atomicMax(&sNon, locNon);
        atomicMax(&sWrong, locWrong);
        atomicOr(&sPres, locPres);
    }
    __syncthreads();

    if (threadIdx.x == 0) {
        unsigned pres = sPres;
        float loss;
        if (pres) {
            int fl = __ffs(pres) - 1;
            float x1 = sigmoidf_(dec_f(sG[fl]));
            loss = rank_loss_(x1, 0.5f);
        } else {
            float mNon   = sigmoidf_(dec_f(sNon));
            float mWrong = sigmoidf_(dec_f(sWrong));
            loss = 0.5f * rank_loss_(0.5f, mNon)
                 + 0.5f * rank_loss_(0.5f, mWrong);
        }
        atomicAdd(out, loss);
    }
}

// ---------------------------------------------------------------------------
extern "C" void kernel_launch(void* const* d_in, const int* in_sizes, int n_in,
                              void* d_out, int out_size) {
    const float* x    = (const float*)d_in[0];
    const int*   y    = (const int*)d_in[1];
    const int*   yneg = (const int*)d_in[2];
    const void*  wl   = d_in[3];

    const int C = 9605;
    const int L = in_sizes[3] / C;            // 20
    const int B = in_sizes[0] / C;            // 4096

    float* out = (float*)d_out;

    init_kernel<<<1, 256>>>(out, out_size, (const unsigned int*)wl, 256);
    build_bits_kernel<<<(C + 255) / 256, 256>>>(wl, C, L);
    compact_kernel<<<(C + 255) / 256, 256>>>(C);
    row_loss_kernel<<<B, 256>>>(x, y, yneg, C, out);
}

// round 4
// speedup vs baseline: 2.5732x; 1.0503x over previous
#include <cuda_runtime.h>
#include <cuda_bf16.h>
#include <math.h>

// ---------------------------------------------------------------------------
// AsymmetricLossCustomPriorityRankNewNegOne  (B=4096, C=9605, L=20)
// Fast path (device-verified): union contiguous [cmin, cmin+n), one group per
// class, gid(j) == (j*M)>>22 == floor(j/gs). Two-phase row kernel:
//   phase 1: scan y only -> presence bits
//   phase 2: wl branch   -> one warp reads the 50 x's of the first group
//            other branch-> scan x & y_neg with plain fmaxf
// ---------------------------------------------------------------------------

#define MAXC 16384

__device__ unsigned            g_bits[MAXC];
__device__ unsigned long long  g_pack[MAXC];   // (bits<<32 | c)  [slow path]
__device__ int                 g_ucount;
__device__ int                 g_cmin;
__device__ int                 g_cmax;
__device__ int                 g_notfast;
__device__ int                 g_gs;           // uniform group size candidate
__device__ int                 g_is_u8;

__device__ __forceinline__ unsigned enc_f(float f) {
    unsigned u = __float_as_uint(f);
    return (u & 0x80000000u) ? ~u : (u | 0x80000000u);
}
__device__ __forceinline__ float dec_f(unsigned u) {
    return __uint_as_float((u & 0x80000000u) ? (u & 0x7fffffffu) : ~u);
}
__device__ __forceinline__ float sigmoidf_(float x) {
    return 1.0f / (1.0f + expf(-x));
}
// d = x2 - x1 + 0.05; s = sigmoid(10 d); d>0 -> 2s else s
__device__ __forceinline__ float rank_loss_(float x1, float x2) {
    float d = x2 - x1 + 0.05f;
    float s = sigmoidf_(10.0f * d);
    return (d > 0.0f) ? 2.0f * s : s;
}

// --- kernel 1: init + parallel width detect ----------------------------------
__global__ void init_kernel(float* out, int out_size,
                            const unsigned int* wl_as_u32, int n_probe) {
    __shared__ int flag;
    int t = threadIdx.x;
    if (t == 0) flag = 0;
    __syncthreads();
    for (int i = t; i < out_size; i += blockDim.x) out[i] = 0.0f;
    if (t < n_probe && wl_as_u32[t] > 1u) flag = 1;
    __syncthreads();
    if (t == 0) {
        g_is_u8   = flag;
        g_ucount  = 0;
        g_cmin    = 0x7fffffff;
        g_cmax    = -1;
        g_notfast = 0;
        g_gs      = 0;
    }
}

// --- kernel 2: per-class group bitmask + stats ---------------------------------
__global__ void build_bits_kernel(const void* wl, int C, int L) {
    __shared__ int bmin, bmax, bbad, bgs;
    if (threadIdx.x == 0) { bmin = 0x7fffffff; bmax = -1; bbad = 0; bgs = 0; }
    __syncthreads();

    int c = blockIdx.x * blockDim.x + threadIdx.x;
    unsigned b = 0;
    if (c < C) {
        if (g_is_u8) {
            const unsigned char* m = (const unsigned char*)wl;
            #pragma unroll 4
            for (int l = 0; l < L; l++)
                if (m[(size_t)l * C + c]) b |= (1u << l);
        } else {
            const int* m = (const int*)wl;
            #pragma unroll 4
            for (int l = 0; l < L; l++)
                if (m[(size_t)l * C + c]) b |= (1u << l);
        }
        g_bits[c] = b;
        if (b) {
            atomicMin(&bmin, c);
            atomicMax(&bmax, c);
            if (__popc(b) > 1) bbad = 1;
            if (b == 1u) atomicAdd(&bgs, 1);
        }
    }
    __syncthreads();
    if (threadIdx.x == 0) {
        if (bmax >= 0) { atomicMin(&g_cmin, bmin); atomicMax(&g_cmax, bmax); }
        if (bbad) g_notfast = 1;
        if (bgs)  atomicAdd(&g_gs, bgs);
    }
}

// --- kernel 3: compaction + exact fast-path verification -----------------------
__global__ void compact_kernel(int C) {
    __shared__ int woff[8];
    __shared__ int sbase;
    int c    = blockIdx.x * 256 + threadIdx.x;
    int lane = threadIdx.x & 31;
    int wid  = threadIdx.x >> 5;

    unsigned b = (c < C) ? g_bits[c] : 0u;
    unsigned ballot = __ballot_sync(0xffffffffu, b != 0u);
    if (lane == 0) woff[wid] = __popc(ballot);
    __syncthreads();
    if (threadIdx.x == 0) {
        int acc = 0;
        #pragma unroll
        for (int w = 0; w < 8; w++) { int t = woff[w]; woff[w] = acc; acc += t; }
        sbase = atomicAdd(&g_ucount, acc);
    }
    __syncthreads();
    if (b) {
        int pos = sbase + woff[wid] + __popc(ballot & ((1u << lane) - 1u));
        g_pack[pos] = ((unsigned long long)b << 32) | (unsigned)c;

        int gs = g_gs;
        if (gs > 0) {
            unsigned M = (4194304u + (unsigned)gs - 1u) / (unsigned)gs;
            unsigned j = (unsigned)(c - g_cmin);
            unsigned gm = (j * M) >> 22;
            if ((int)gm != (__ffs(b) - 1) || gm >= 32u) g_notfast = 1;
        } else {
            g_notfast = 1;
        }
    }
}

// --- kernel 4: per-row loss, two-phase ------------------------------------------
__global__ __launch_bounds__(256)
void row_loss_kernel(const float* __restrict__ x,
                     const int*   __restrict__ y,
                     const int*   __restrict__ yneg,
                     int C, float* __restrict__ out) {
    const unsigned KNEG = enc_f(-1e30f);

    __shared__ unsigned sG[32];          // slow path only
    __shared__ unsigned sPres, sNon, sWrong;

    if (threadIdx.x < 32) sG[threadIdx.x] = KNEG;
    if (threadIdx.x == 0) { sPres = 0u; sNon = KNEG; sWrong = KNEG; }
    __syncthreads();

    const int row  = blockIdx.x;
    const int n    = g_ucount;
    const int cmin = g_cmin;
    const bool fast = (!g_notfast) && (g_cmax - cmin + 1 == n);
    const long long base = (long long)row * C + cmin;

    if (fast) {
        const int gs = g_gs;
        const unsigned M = (4194304u + (unsigned)gs - 1u) / (unsigned)gs;
        const float* __restrict__ xr  = x    + base;
        const int*   __restrict__ yr  = y    + base;
        const int*   __restrict__ ynr = yneg + base;

        int p = (int)((4 - (base & 3)) & 3);
        if (p > n) p = n;
        const int nv = (n - p) >> 2;
        const int ts = p + 4 * nv;
        const int ntail = n - ts;

        // ---- phase 1: presence from y only ----
        unsigned locPres = 0u;
        for (int i = threadIdx.x; i < nv; i += 256) {
            const int j0 = p + 4 * i;
            const int4 yv = *(const int4*)(yr + j0);
            if (yv.x | yv.y | yv.z | yv.w) {          // rare (~1% density)
                if (yv.x) locPres |= 1u << (((unsigned)(j0    ) * M) >> 22);
                if (yv.y) locPres |= 1u << (((unsigned)(j0 + 1) * M) >> 22);
                if (yv.z) locPres |= 1u << (((unsigned)(j0 + 2) * M) >> 22);
                if (yv.w) locPres |= 1u << (((unsigned)(j0 + 3) * M) >> 22);
            }
        }
        for (int t = threadIdx.x; t < p + ntail; t += 256) {
            const int j = (t < p) ? t : (ts + (t - p));
            if (__ldg(yr + j)) locPres |= 1u << (((unsigned)j * M) >> 22);
        }
        #pragma unroll
        for (int off = 16; off > 0; off >>= 1)
            locPres |= __shfl_xor_sync(0xffffffffu, locPres, off);
        if ((threadIdx.x & 31) == 0 && locPres) atomicOr(&sPres, locPres);
        __syncthreads();

        const unsigned pres = sPres;
        if (pres) {
            // ---- phase 2a: one warp reads the first-present group's x ----
            if (threadIdx.x < 32) {
                const int fl = __ffs(pres) - 1;
                const int j0 = fl * gs;
                float m = -1e30f;
                for (int t = threadIdx.x; t < gs && j0 + t < n; t += 32)
                    m = fmaxf(m, __ldg(xr + j0 + t));
                #pragma unroll
                for (int off = 16; off > 0; off >>= 1)
                    m = fmaxf(m, __shfl_xor_sync(0xffffffffu, m, off));
                if (threadIdx.x == 0)
                    atomicAdd(out, rank_loss_(sigmoidf_(m), 0.5f));
            }
        } else {
            // ---- phase 2b: union max of x, and y_neg-masked max ----
            float mN = -1e30f, mW = -1e30f;
            for (int i = threadIdx.x; i < nv; i += 256) {
                const int j0 = p + 4 * i;
                const float4 xv  = *(const float4*)(xr  + j0);
                const int4   ynv = *(const int4*)  (ynr + j0);
                mN = fmaxf(mN, fmaxf(fmaxf(xv.x, xv.y), fmaxf(xv.z, xv.w)));
                if (ynv.x) mW = fmaxf(mW, xv.x);
                if (ynv.y) mW = fmaxf(mW, xv.y);
                if (ynv.z) mW = fmaxf(mW, xv.z);
                if (ynv.w) mW = fmaxf(mW, xv.w);
            }
            for (int t = threadIdx.x; t < p + ntail; t += 256) {
                const int j = (t < p) ? t : (ts + (t - p));
                const float xv = __ldg(xr + j);
                mN = fmaxf(mN, xv);
                if (__ldg(ynr + j)) mW = fmaxf(mW, xv);
            }
            #pragma unroll
            for (int off = 16; off > 0; off >>= 1) {
                mN = fmaxf(mN, __shfl_xor_sync(0xffffffffu, mN, off));
                mW = fmaxf(mW, __shfl_xor_sync(0xffffffffu, mW, off));
            }
            if ((threadIdx.x & 31) == 0) {
                atomicMax(&sNon,   enc_f(mN));
                atomicMax(&sWrong, enc_f(mW));
            }
            __syncthreads();
            if (threadIdx.x == 0) {
                const float mNon   = sigmoidf_(dec_f(sNon));
                const float mWrong = sigmoidf_(dec_f(sWrong));
                atomicAdd(out, 0.5f * rank_loss_(0.5f, mNon)
                             + 0.5f * rank_loss_(0.5f, mWrong));
            }
        }
        return;
    }

    // ---------------- generic slow path ----------------
    unsigned locNon = KNEG, locWrong = KNEG, locPres = 0u;
    for (int i = threadIdx.x; i < n; i += 256) {
        unsigned long long pk = g_pack[i];
        int c         = (int)(pk & 0xffffffffull);
        unsigned bits = (unsigned)(pk >> 32);
        const long long o = (long long)row * C + c;
        float xv = __ldg(x + o);
        unsigned key = enc_f(xv);
        locNon = max(locNon, key);
        if (__ldg(yneg + o) != 0) locWrong = max(locWrong, key);
        if (__ldg(y    + o) != 0) locPres |= bits;
        unsigned bb = bits;
        while (bb) {
            int l = __ffs(bb) - 1;
            bb &= bb - 1u;
            atomicMax(&sG[l], key);
        }
    }
    #pragma unroll
    for (int off = 16; off > 0; off >>= 1) {
        locNon   = max(locNon,   __shfl_down_sync(0xffffffffu, locNon,   off));
        locWrong = max(locWrong, __shfl_down_sync(0xffffffffu, locWrong, off));
        locPres |= __shfl_down_sync(0xffffffffu, locPres, off);
    }
    if ((threadIdx.x & 31) == 0) {
        atomicMax(&sNon, locNon);
        atomicMax(&sWrong, locWrong);
        atomicOr(&sPres, locPres);
    }
    __syncthreads();
    if (threadIdx.x == 0) {
        unsigned pres = sPres;
        float loss;
        if (pres) {
            int fl = __ffs(pres) - 1;
            loss = rank_loss_(sigmoidf_(dec_f(sG[fl])), 0.5f);
        } else {
            loss = 0.5f * rank_loss_(0.5f, sigmoidf_(dec_f(sNon)))
                 + 0.5f * rank_loss_(0.5f, sigmoidf_(dec_f(sWrong)));
        }
        atomicAdd(out, loss);
    }
}

// ---------------------------------------------------------------------------
extern "C" void kernel_launch(void* const* d_in, const int* in_sizes, int n_in,
                              void* d_out, int out_size) {
    const float* x    = (const float*)d_in[0];
    const int*   y    = (const int*)d_in[1];
    const int*   yneg = (const int*)d_in[2];
    const void*  wl   = d_in[3];

    const int C = 9605;
    const int L = in_sizes[3] / C;            // 20
    const int B = in_sizes[0] / C;            // 4096

    float* out = (float*)d_out;

    init_kernel<<<1, 256>>>(out, out_size, (const unsigned int*)wl, 256);
    build_bits_kernel<<<(C + 255) / 256, 256>>>(wl, C, L);
    compact_kernel<<<(C + 255) / 256, 256>>>(C);
    row_loss_kernel<<<B, 256>>>(x, y, yneg, C, out);
}

// round 5
// speedup vs baseline: 3.1610x; 1.2285x over previous
#include <cuda_runtime.h>
#include <cuda_bf16.h>
#include <math.h>

// ---------------------------------------------------------------------------
// AsymmetricLossCustomPriorityRankNewNegOne  (B=4096, C=9605, L=20)
// Warp-per-row, single ordered fused scan with early exit on first y positive
// (group id monotone in column => first positive column = priority group).
// Fast path is device-verified; generic slow path kept.
// ---------------------------------------------------------------------------

#define MAXC 16384

__device__ unsigned            g_bits[MAXC];
__device__ unsigned long long  g_pack[MAXC];   // (bits<<32 | c)  [slow path]
__device__ int                 g_ucount;
__device__ int                 g_cmin;
__device__ int                 g_cmax;
__device__ int                 g_notfast;
__device__ int                 g_gs;           // uniform group size candidate
__device__ int                 g_is_u8;

__device__ __forceinline__ unsigned enc_f(float f) {
    unsigned u = __float_as_uint(f);
    return (u & 0x80000000u) ? ~u : (u | 0x80000000u);
}
__device__ __forceinline__ float dec_f(unsigned u) {
    return __uint_as_float((u & 0x80000000u) ? (u & 0x7fffffffu) : ~u);
}
__device__ __forceinline__ float sigmoidf_(float x) {
    return 1.0f / (1.0f + expf(-x));
}
// d = x2 - x1 + 0.05; s = sigmoid(10 d); d>0 -> 2s else s
__device__ __forceinline__ float rank_loss_(float x1, float x2) {
    float d = x2 - x1 + 0.05f;
    float s = sigmoidf_(10.0f * d);
    return (d > 0.0f) ? 2.0f * s : s;
}

// --- kernel 1: init + parallel width detect ----------------------------------
__global__ void init_kernel(float* out, int out_size,
                            const unsigned int* wl_as_u32, int n_probe) {
    __shared__ int flag;
    int t = threadIdx.x;
    if (t == 0) flag = 0;
    __syncthreads();
    for (int i = t; i < out_size; i += blockDim.x) out[i] = 0.0f;
    if (t < n_probe && wl_as_u32[t] > 1u) flag = 1;
    __syncthreads();
    if (t == 0) {
        g_is_u8   = flag;
        g_ucount  = 0;
        g_cmin    = 0x7fffffff;
        g_cmax    = -1;
        g_notfast = 0;
        g_gs      = 0;
    }
}

// --- kernel 2: per-class group bitmask + stats ---------------------------------
__global__ void build_bits_kernel(const void* wl, int C, int L) {
    __shared__ int bmin, bmax, bbad, bgs;
    if (threadIdx.x == 0) { bmin = 0x7fffffff; bmax = -1; bbad = 0; bgs = 0; }
    __syncthreads();

    int c = blockIdx.x * blockDim.x + threadIdx.x;
    unsigned b = 0;
    if (c < C) {
        if (g_is_u8) {
            const unsigned char* m = (const unsigned char*)wl;
            #pragma unroll 4
            for (int l = 0; l < L; l++)
                if (m[(size_t)l * C + c]) b |= (1u << l);
        } else {
            const int* m = (const int*)wl;
            #pragma unroll 4
            for (int l = 0; l < L; l++)
                if (m[(size_t)l * C + c]) b |= (1u << l);
        }
        g_bits[c] = b;
        if (b) {
            atomicMin(&bmin, c);
            atomicMax(&bmax, c);
            if (__popc(b) > 1) bbad = 1;
            if (b == 1u) atomicAdd(&bgs, 1);
        }
    }
    __syncthreads();
    if (threadIdx.x == 0) {
        if (bmax >= 0) { atomicMin(&g_cmin, bmin); atomicMax(&g_cmax, bmax); }
        if (bbad) g_notfast = 1;
        if (bgs)  atomicAdd(&g_gs, bgs);
    }
}

// --- kernel 3: compaction + exact fast-path verification -----------------------
__global__ void compact_kernel(int C) {
    __shared__ int woff[8];
    __shared__ int sbase;
    int c    = blockIdx.x * 256 + threadIdx.x;
    int lane = threadIdx.x & 31;
    int wid  = threadIdx.x >> 5;

    unsigned b = (c < C) ? g_bits[c] : 0u;
    unsigned ballot = __ballot_sync(0xffffffffu, b != 0u);
    if (lane == 0) woff[wid] = __popc(ballot);
    __syncthreads();
    if (threadIdx.x == 0) {
        int acc = 0;
        #pragma unroll
        for (int w = 0; w < 8; w++) { int t = woff[w]; woff[w] = acc; acc += t; }
        sbase = atomicAdd(&g_ucount, acc);
    }
    __syncthreads();
    if (b) {
        int pos = sbase + woff[wid] + __popc(ballot & ((1u << lane) - 1u));
        g_pack[pos] = ((unsigned long long)b << 32) | (unsigned)c;

        int gs = g_gs;
        if (gs > 0) {
            unsigned M = (4194304u + (unsigned)gs - 1u) / (unsigned)gs;
            unsigned j = (unsigned)(c - g_cmin);
            unsigned gm = (j * M) >> 22;
            if ((int)gm != (__ffs(b) - 1) || gm >= 32u) g_notfast = 1;
        } else {
            g_notfast = 1;
        }
    }
}

// --- kernel 4: warp-per-row loss -------------------------------------------------
__global__ __launch_bounds__(256)
void row_loss_kernel(const float* __restrict__ x,
                     const int*   __restrict__ y,
                     const int*   __restrict__ yneg,
                     int C, int B, float* __restrict__ out) {
    __shared__ float sSum;
    __shared__ unsigned sG[8][32];           // slow path per-warp group maxes

    const int lane = threadIdx.x & 31;
    const int wid  = threadIdx.x >> 5;
    const int row  = blockIdx.x * 8 + wid;

    if (threadIdx.x == 0) sSum = 0.0f;
    __syncthreads();

    const int n    = g_ucount;
    const int cmin = g_cmin;
    const bool fast = (!g_notfast) && (g_cmax - cmin + 1 == n);

    float warp_loss = 0.0f;

    if (row < B && fast) {
        const int gs = g_gs;
        const unsigned M = (4194304u + (unsigned)gs - 1u) / (unsigned)gs;
        const long long base = (long long)row * C + cmin;
        const float* __restrict__ xr  = x    + base;
        const int*   __restrict__ yr  = y    + base;
        const int*   __restrict__ ynr = yneg + base;

        int p = (int)((4 - (base & 3)) & 3);
        if (p > n) p = n;
        const int nv = (n - p) >> 2;          // vec4 chunks
        const int ts = p + 4 * nv;
        const int ntail = n - ts;

        float mN = -1e30f, mW = -1e30f;
        bool found = false;
        int  jmin  = 0x7fffffff;

        // ---- ordered peel [0, p) ----
        {
            int yv = 0;
            if (lane < p) {
                const int j = lane;
                yv = __ldg(yr + j);
                const float xv = __ldg(xr + j);
                mN = fmaxf(mN, xv);
                if (__ldg(ynr + j)) mW = fmaxf(mW, xv);
            }
            unsigned bal = __ballot_sync(0xffffffffu, yv != 0);
            if (bal) { jmin = __ffs(bal) - 1; found = true; }
        }

        // ---- ordered vec4 scan, 32 chunks (128 elems) per iteration ----
        if (!found) {
            for (int t0 = 0; t0 < nv; t0 += 32) {
                const int i   = t0 + lane;
                const bool act = (i < nv);
                const int j0  = p + 4 * i;
                int4 yv = make_int4(0, 0, 0, 0);
                if (act) {
                    yv = *(const int4*)(yr + j0);
                    const float4 xv  = *(const float4*)(xr  + j0);
                    const int4   ynv = *(const int4*)(ynr + j0);
                    mN = fmaxf(mN, fmaxf(fmaxf(xv.x, xv.y), fmaxf(xv.z, xv.w)));
                    if (ynv.x) mW = fmaxf(mW, xv.x);
                    if (ynv.y) mW = fmaxf(mW, xv.y);
                    if (ynv.z) mW = fmaxf(mW, xv.z);
                    if (ynv.w) mW = fmaxf(mW, xv.w);
                }
                unsigned bal = __ballot_sync(0xffffffffu,
                                             (yv.x | yv.y | yv.z | yv.w) != 0);
                if (bal) {
                    int lj = 0x7fffffff;
                    if (yv.w) lj = j0 + 3;
                    if (yv.z) lj = j0 + 2;
                    if (yv.y) lj = j0 + 1;
                    if (yv.x) lj = j0;
                    #pragma unroll
                    for (int off = 16; off > 0; off >>= 1)
                        lj = min(lj, __shfl_xor_sync(0xffffffffu, lj, off));
                    jmin = lj;
                    found = true;
                    break;
                }
            }
        }

        // ---- ordered tail [ts, n) ----
        if (!found && ntail > 0) {
            int yv = 0;
            if (lane < ntail) {
                const int j = ts + lane;
                yv = __ldg(yr + j);
                const float xv = __ldg(xr + j);
                mN = fmaxf(mN, xv);
                if (__ldg(ynr + j)) mW = fmaxf(mW, xv);
            }
            unsigned bal = __ballot_sync(0xffffffffu, yv != 0);
            if (bal) { jmin = ts + __ffs(bal) - 1; found = true; }
        }

        if (found) {
            // priority group = group of first positive column (gid monotone in j)
            const int fl = (int)(((unsigned)jmin * M) >> 22);
            const int j0 = fl * gs;
            float m = -1e30f;
            for (int t = lane; t < gs; t += 32) {
                const int j = j0 + t;
                if (j < n) m = fmaxf(m, __ldg(xr + j));
            }
            #pragma unroll
            for (int off = 16; off > 0; off >>= 1)
                m = fmaxf(m, __shfl_xor_sync(0xffffffffu, m, off));
            warp_loss = rank_loss_(sigmoidf_(m), 0.5f);
        } else {
            #pragma unroll
            for (int off = 16; off > 0; off >>= 1) {
                mN = fmaxf(mN, __shfl_xor_sync(0xffffffffu, mN, off));
                mW = fmaxf(mW, __shfl_xor_sync(0xffffffffu, mW, off));
            }
            warp_loss = 0.5f * rank_loss_(0.5f, sigmoidf_(mN))
                      + 0.5f * rank_loss_(0.5f, sigmoidf_(mW));
        }
    } else if (row < B) {
        // ---------------- generic slow path (warp-per-row) ----------------
        const unsigned KNEG = enc_f(-1e30f);
        sG[wid][lane] = KNEG;
        __syncwarp();

        unsigned locNon = KNEG, locWrong = KNEG, locPres = 0u;
        for (int i = lane; i < n; i += 32) {
            const unsigned long long pk = g_pack[i];
            const int c         = (int)(pk & 0xffffffffull);
            const unsigned bits = (unsigned)(pk >> 32);
            const long long o = (long long)row * C + c;
            const float xv = __ldg(x + o);
            const unsigned key = enc_f(xv);
            locNon = max(locNon, key);
            if (__ldg(yneg + o) != 0) locWrong = max(locWrong, key);
            if (__ldg(y    + o) != 0) locPres |= bits;
            unsigned bb = bits;
            while (bb) {
                const int l = __ffs(bb) - 1;
                bb &= bb - 1u;
                atomicMax(&sG[wid][l], key);
            }
        }
        #pragma unroll
        for (int off = 16; off > 0; off >>= 1) {
            locNon   = max(locNon,   __shfl_xor_sync(0xffffffffu, locNon,   off));
            locWrong = max(locWrong, __shfl_xor_sync(0xffffffffu, locWrong, off));
            locPres |= __shfl_xor_sync(0xffffffffu, locPres, off);
        }
        __syncwarp();
        if (lane == 0) {
            if (locPres) {
                const int fl = __ffs(locPres) - 1;
                warp_loss = rank_loss_(sigmoidf_(dec_f(sG[wid][fl])), 0.5f);
            } else {
                warp_loss = 0.5f * rank_loss_(0.5f, sigmoidf_(dec_f(locNon)))
                          + 0.5f * rank_loss_(0.5f, sigmoidf_(dec_f(locWrong)));
            }
        }
    }

    if (lane == 0 && row < B) atomicAdd(&sSum, warp_loss);
    __syncthreads();
    if (threadIdx.x == 0) atomicAdd(out, sSum);
}

// ---------------------------------------------------------------------------
extern "C" void kernel_launch(void* const* d_in, const int* in_sizes, int n_in,
                              void* d_out, int out_size) {
    const float* x    = (const float*)d_in[0];
    const int*   y    = (const int*)d_in[1];
    const int*   yneg = (const int*)d_in[2];
    const void*  wl   = d_in[3];

    const int C = 9605;
    const int L = in_sizes[3] / C;            // 20
    const int B = in_sizes[0] / C;            // 4096

    float* out = (float*)d_out;

    init_kernel<<<1, 256>>>(out, out_size, (const unsigned int*)wl, 256);
    build_bits_kernel<<<(C + 255) / 256, 256>>>(wl, C, L);
    compact_kernel<<<(C + 255) / 256, 256>>>(C);
    row_loss_kernel<<<(B + 7) / 8, 256>>>(x, y, yneg, C, B, out);
}